// round 16
// baseline (speedup 1.0000x reference)
#include <cuda_runtime.h>

typedef unsigned long long ull;

#define HH 192
#define BB 16
#define NPIX (BB*2*HH*HH)

// ---------- packed f32x2 helpers (sm_103a) ----------
__device__ __forceinline__ ull pk2(float x, float y){ ull r; asm("mov.b64 %0,{%1,%2};":"=l"(r):"f"(x),"f"(y)); return r; }
__device__ __forceinline__ ull dup2(float x){ return pk2(x,x); }
__device__ __forceinline__ void unpk2(ull v, float&x, float&y){ asm("mov.b64 {%0,%1},%2;":"=f"(x),"=f"(y):"l"(v)); }
__device__ __forceinline__ ull ffma2(ull a, ull b, ull c){ ull d; asm("fma.rn.f32x2 %0,%1,%2,%3;":"=l"(d):"l"(a),"l"(b),"l"(c)); return d; }
__device__ __forceinline__ ull fmul2(ull a, ull b){ ull d; asm("mul.rn.f32x2 %0,%1,%2;":"=l"(d):"l"(a),"l"(b)); return d; }
__device__ __forceinline__ ull fadd2(ull a, ull b){ ull d; asm("add.rn.f32x2 %0,%1,%2;":"=l"(d):"l"(a),"l"(b)); return d; }

// ---------- packed constants, 16B-vectorized ----------
struct ConstBlob {
  ulonglong2 kp[3][25];  // kp[p][i*5+j] = (stencil 2p, stencil 2p+1) tap, lanes dup
  ulonglong2 w0p[12];    // .x = p weight(i), .y = q weight(i); lanes = poly k0,k1
  ulonglong2 w1p[13];    // .x = r, .y = s
  ulonglong2 b01;        // .x = b0(p), .y = b0(q)
  ulonglong2 b11;        // .x = b1(r), .y = b1(s)
  ulonglong2 gw0p[2];    // [off-1]; .x = u=0 pack, .y = u=1 pack
  ulonglong2 gw1p[2];
  ull wf[14];
  ull bf;
  ull gwf[2];
};

__constant__ ConstBlob cb;
__device__ ConstBlob g_stage;
__device__ float g_uh[NPIX];
__device__ float g_ua[NPIX];
__device__ float g_ub[NPIX];

__global__ void prep_kernel(const float* __restrict__ kern,
                            const float* __restrict__ w0, const float* __restrict__ b0,
                            const float* __restrict__ w1, const float* __restrict__ b1,
                            const float* __restrict__ wf, const float* __restrict__ bf)
{
  int t = threadIdx.x;
  const double dDX = 0.0327249;
  const float s1 = (float)(1.0/dDX);
  const float s2 = (float)(1.0/(dDX*dDX));
  const float sc[6] = {1.f, s1, s1, s2, s2, s2};
  if (t < 75) {
    int p = t/25, e = t%25;
    int d0 = 2*p, d1 = 2*p+1;
    ulonglong2 v;
    v.x = dup2(kern[d0*25 + e] * sc[d0]);
    v.y = dup2(kern[d1*25 + e] * sc[d1]);
    g_stage.kp[p][e] = v;
  }
  if (t == 0) {
    for (int i = 0; i < 12; i++) {
      ulonglong2 a;
      a.x = pk2(w0[i],    w0[24+i]);
      a.y = pk2(w0[12+i], w0[24+12+i]);
      g_stage.w0p[i] = a;
    }
    for (int i = 0; i < 13; i++) {
      ulonglong2 a;
      a.x = pk2(w1[i],    w1[26+i]);
      a.y = pk2(w1[13+i], w1[26+13+i]);
      g_stage.w1p[i] = a;
    }
    { ulonglong2 a; a.x = pk2(b0[0], b0[2]); a.y = pk2(b0[1], b0[3]); g_stage.b01 = a; }
    { ulonglong2 a; a.x = pk2(b1[0], b1[2]); a.y = pk2(b1[1], b1[3]); g_stage.b11 = a; }
    for (int i = 0; i < 14; i++) g_stage.wf[i] = pk2(wf[i], wf[14+i]);
    g_stage.bf = pk2(bf[0], bf[1]);
    for (int o = 0; o < 2; o++) {
      ulonglong2 a, c;
      a.x = pk2(w0[1+o],      w0[24 + 7+o]);
      a.y = pk2(w0[12 + 1+o], w0[24 + 12 + 7+o]);
      g_stage.gw0p[o] = a;
      c.x = pk2(w1[1+o],      w1[26 + 7+o]);
      c.y = pk2(w1[13 + 1+o], w1[26 + 13 + 7+o]);
      g_stage.gw1p[o] = c;
      g_stage.gwf[o] = pk2(wf[1+o], wf[14 + 7+o]);
    }
  }
}

// out = ubase + coef * rhs(ueval); 1 pixel/thread, 32x6 blocks, 7 blocks/SM.
// PDL: prologue (index math) runs overlapped with the previous kernel's tail;
// cudaGridDependencySynchronize() gates the first data-dependent load.
// same_base != 0 means ub == ue (output base pair comes from the smem tile).
__global__ __launch_bounds__(192, 7)
void rhs_step(const float* __restrict__ ue, const float* __restrict__ ub,
              float coef, float* __restrict__ out, int same_base)
{
  __shared__ ull tile[10][36];   // (c0,c1) packed, rows h0-2 .. h0+7

  const int tx = threadIdx.x, ty = threadIdx.y;
  const int tid = ty*32 + tx;
  const int w0_ = blockIdx.x*32, h0 = blockIdx.y*6, b = blockIdx.z;

  const float* u0 = ue + (size_t)b*2*HH*HH;
  const float* u1 = u0 + HH*HH;

  // precompute halo addresses (independent of upstream data)
  int rr[2], cc[2];
  #pragma unroll
  for (int q = 0; q < 2; q++) {
    int e = tid + q*192;
    int r = e/36, c = e%36;
    int hh = h0 + r - 2; if (hh < 0) hh += HH; if (hh >= HH) hh -= HH;
    int ww = w0_ + c - 2; if (ww < 0) ww += HH; if (ww >= HH) ww -= HH;
    rr[q] = (e < 360) ? (hh*HH + ww) : -1;
    cc[q] = e;
  }

  // wait for upstream kernel's writes to become visible
  cudaGridDependencySynchronize();

  #pragma unroll
  for (int q = 0; q < 2; q++) {
    if (rr[q] >= 0) {
      int e = cc[q];
      tile[e/36][e%36] = pk2(u0[rr[q]], u1[rr[q]]);
    }
  }
  __syncthreads();

  // ---- 6 base correlations + 2 mirrored (constants shared via vector loads) ----
  ull a0=0ull,a1=0ull,a2=0ull,a3=0ull,a4=0ull,a5=0ull,t6=0ull,t7=0ull;
  #pragma unroll
  for (int i = 0; i < 5; i++) {
    ull w[5];
    #pragma unroll
    for (int j = 0; j < 5; j++) w[j] = tile[ty+i][tx+j];
    #pragma unroll
    for (int j = 0; j < 5; j++) {
      const ulonglong2 k01 = cb.kp[0][i*5+j];
      const ulonglong2 k23 = cb.kp[1][i*5+j];
      const ulonglong2 k45 = cb.kp[2][i*5+j];
      a0 = ffma2(k01.x, w[j], a0);
      a1 = ffma2(k01.y, w[j], a1);
      a2 = ffma2(k23.x, w[j], a2);
      a3 = ffma2(k23.y, w[j], a3);
      a4 = ffma2(k45.x, w[j], a4);
      a5 = ffma2(k45.y, w[j], a5);
      // f01 = -sum k01tap(i,j)*w(i,4-j): width mirror
      t6 = ffma2(k01.y, w[4-j], t6);
      // f10 = -sum k10tap(i,j)*w(4-i,j): height mirror (const CSE across unroll)
      t7 = ffma2(cb.kp[1][(4-i)*5+j].x, w[j], t7);
    }
  }

  float X[12];
  unpk2(a0, X[0], X[6]); unpk2(a1, X[1], X[7]); unpk2(a2, X[2], X[8]);
  unpk2(a3, X[3], X[9]); unpk2(a4, X[4], X[10]); unpk2(a5, X[5], X[11]);
  float n6x, n6y, n7x, n7y;
  unpk2(t6, n6x, n6y);   // f01 = -n6
  unpk2(t7, n7x, n7y);   // f10 = -n7

  // ---- poly linear parts at base (lanes = poly k0,k1) ----
  ull p2 = cb.b01.x, q2 = cb.b01.y, rl = cb.b11.x, sl = cb.b11.y, ol = cb.bf;
  #pragma unroll
  for (int i = 0; i < 12; i++) {
    ull xd = dup2(X[i]);
    const ulonglong2 wa = cb.w0p[i];
    const ulonglong2 wb = cb.w1p[i];
    p2 = ffma2(wa.x, xd, p2);
    q2 = ffma2(wa.y, xd, q2);
    rl = ffma2(wb.x, xd, rl);
    sl = ffma2(wb.y, xd, sl);
    ol = ffma2(cb.wf[i], xd, ol);
  }
  const ulonglong2 wm = cb.w1p[12];   // m1 coefficients for (r,s)
  ull m1 = fmul2(p2, q2);
  ull r2 = ffma2(wm.x, m1, rl);
  ull s2 = ffma2(wm.y, m1, sl);

  // ---- analytic gradient at base: d(poly_k)/dX[k*6+off], off=1,2 ----
  ull g2[2];
  #pragma unroll
  for (int o = 0; o < 2; o++) {
    const ulonglong2 ga = cb.gw0p[o];
    const ulonglong2 gc = cb.gw1p[o];
    ull dm1 = fadd2(fmul2(q2, ga.x), fmul2(p2, ga.y));
    ull dr  = ffma2(wm.x, dm1, gc.x);
    ull ds  = ffma2(wm.y, dm1, gc.y);
    ull dm2 = fadd2(fmul2(s2, dr), fmul2(r2, ds));
    ull g   = ffma2(cb.wf[12], dm1, cb.gwf[o]);
    g2[o]   = ffma2(cb.wf[13], dm2, g);
  }
  float g01a, g01b, g10a, g10b;
  unpk2(g2[0], g01a, g01b);
  unpk2(g2[1], g10a, g10b);

  // upwind deltas (0 if keep base, else flipped - base); flipped = -n
  float d1 = (g01a > 0.f) ? 0.f : (-n6x - X[1]);
  float d7 = (g01b > 0.f) ? 0.f : (-n6y - X[7]);
  float d2 = (g10a > 0.f) ? 0.f : (-n7x - X[2]);
  float d8 = (g10b > 0.f) ? 0.f : (-n7y - X[8]);
  ull D1 = dup2(d1), D2 = dup2(d2), D7 = dup2(d7), D8 = dup2(d8);

  // ---- delta-update linear parts to Xsel, finish poly ----
  {
    const ulonglong2 c1 = cb.w0p[1], c2 = cb.w0p[2], c7 = cb.w0p[7], c8 = cb.w0p[8];
    p2 = ffma2(c1.x, D1, ffma2(c2.x, D2, ffma2(c7.x, D7, ffma2(c8.x, D8, p2))));
    q2 = ffma2(c1.y, D1, ffma2(c2.y, D2, ffma2(c7.y, D7, ffma2(c8.y, D8, q2))));
  }
  {
    const ulonglong2 c1 = cb.w1p[1], c2 = cb.w1p[2], c7 = cb.w1p[7], c8 = cb.w1p[8];
    rl = ffma2(c1.x, D1, ffma2(c2.x, D2, ffma2(c7.x, D7, ffma2(c8.x, D8, rl))));
    sl = ffma2(c1.y, D1, ffma2(c2.y, D2, ffma2(c7.y, D7, ffma2(c8.y, D8, sl))));
  }
  ol = ffma2(cb.wf[1], D1, ffma2(cb.wf[2], D2, ffma2(cb.wf[7], D7, ffma2(cb.wf[8], D8, ol))));

  m1 = fmul2(p2, q2);
  r2 = ffma2(wm.x, m1, rl);
  s2 = ffma2(wm.y, m1, sl);
  ull m2 = fmul2(r2, s2);
  ull o2 = ffma2(cb.wf[12], m1, ol);
  o2 = ffma2(cb.wf[13], m2, o2);

  // ---- epilogue: packed base + single FFMA2 ----
  const int h = h0 + ty, w = w0_ + tx;
  const size_t i0 = ((size_t)(b*2))*HH*HH + (size_t)h*HH + w;
  ull ubp;
  if (same_base) {
    ubp = tile[ty+2][tx+2];                 // ub == ue: center pair already in smem
  } else {
    ubp = pk2(ub[i0], ub[i0 + HH*HH]);
  }
  ull res = ffma2(dup2(coef), o2, ubp);
  float r0, r1;
  unpk2(res, r0, r1);
  out[i0]         = r0;
  out[i0 + HH*HH] = r1;
}

extern "C" void kernel_launch(void* const* d_in, const int* in_sizes, int n_in,
                              void* d_out, int out_size)
{
  (void)in_sizes; (void)n_in; (void)out_size;
  const float* init = (const float*)d_in[0];
  const float* kern = (const float*)d_in[1];
  const float* w0   = (const float*)d_in[2];
  const float* b0   = (const float*)d_in[3];
  const float* w1   = (const float*)d_in[4];
  const float* b1   = (const float*)d_in[5];
  const float* wf   = (const float*)d_in[6];
  const float* bf   = (const float*)d_in[7];
  float* out = (float*)d_out;

  void *puh, *pua, *pub, *pstage;
  cudaGetSymbolAddress(&puh, g_uh);
  cudaGetSymbolAddress(&pua, g_ua);
  cudaGetSymbolAddress(&pub, g_ub);
  cudaGetSymbolAddress(&pstage, g_stage);

  prep_kernel<<<1, 128>>>(kern, w0, b0, w1, b1, wf, bf);
  cudaMemcpyToSymbolAsync(cb, pstage, sizeof(ConstBlob), 0, cudaMemcpyDeviceToDevice, 0);

  dim3 grid(HH/32, HH/6, BB);
  dim3 block(32, 6);

  // PDL launch config: allow each rhs_step to start while the previous
  // stream node is draining (kernel gates data reads with
  // cudaGridDependencySynchronize()).
  cudaLaunchAttribute attrs[1];
  attrs[0].id = cudaLaunchAttributeProgrammaticStreamSerialization;
  attrs[0].val.programmaticStreamSerializationAllowed = 1;
  cudaLaunchConfig_t cfg = {};
  cfg.gridDim = grid;
  cfg.blockDim = block;
  cfg.dynamicSmemBytes = 0;
  cfg.stream = 0;
  cfg.attrs = attrs;
  cfg.numAttrs = 1;

  const float DT = 0.2f;
  const float* ucur = init;
  for (int s = 0; s < 5; s++) {
    float* un = (s == 4) ? out : ((s & 1) ? (float*)pub : (float*)pua);
    cudaLaunchKernelEx(&cfg, rhs_step, ucur, ucur, DT*0.5f, (float*)puh, 1);
    cudaLaunchKernelEx(&cfg, rhs_step, (const float*)puh, ucur, DT, un, 0);
    ucur = un;
  }
}